// round 1
// baseline (speedup 1.0000x reference)
#include <cuda_runtime.h>
#include <math.h>

#define NB   2
#define NN   256
#define NF   64
#define NKF  50
#define NHID 64
#define NH   4
#define NC   256
#define DCAT 179   // 2F + KF + 1

// scratch (static device memory; allocation-free)
__device__ float g_he[NB*NN*NF*NN];    // [bi][f][j]  (33.5 MB)
__device__ float g_att[NB*NN*NN*NH];   // [bi][j][hd] (2 MB)

__device__ __forceinline__ float siluf(float v){ return v / (1.f + __expf(-v)); }

// ---------------------------------------------------------------------------
// Kernel A: edge MLP + semantic attention softmax. One block per (b,i),
// thread j handles pair (i,j).
// ---------------------------------------------------------------------------
__global__ __launch_bounds__(256, 1) void k_edge(
    const float* __restrict__ h,     const float* __restrict__ x,
    const float* __restrict__ W_in,  const float* __restrict__ b_in,
    const float* __restrict__ means, const float* __restrict__ betas,
    const float* __restrict__ W_o1,  const float* __restrict__ b_o1,
    const float* __restrict__ W_o2,  const float* __restrict__ b_o2,
    const float* __restrict__ W_sem, const float* __restrict__ b_sem)
{
    extern __shared__ float sm[];
    float* sh_h  = sm;                 // 256*65 (padded rows)
    float* sWin  = sh_h + NN*65;       // 128*50
    float* sWo1  = sWin + 128*NKF;     // 179*64
    float* sWo2  = sWo1 + DCAT*64;     // 64*64
    float* sWsem = sWo2 + 64*64;       // 64*4
    float* sbin  = sWsem + 256;        // 50
    float* smean = sbin + NKF;         // 50
    float* sbeta = smean + NKF;        // 50
    float* sbo1  = sbeta + NKF;        // 64
    float* sbo2  = sbo1 + 64;          // 64
    float* sbsem = sbo2 + 64;          // 4
    float* sx    = sbsem + 4;          // 256*3
    float* sLog  = sx + NN*3;          // 4*256
    float* sRed  = sLog + 4*NN;        // 16

    const int t  = threadIdx.x;
    const int bi = blockIdx.x;
    const int b  = bi >> 8;
    const int i  = bi & 255;

    for (int l = t; l < NN*NF;   l += 256) sh_h[(l>>6)*65 + (l&63)] = h[b*NN*NF + l];
    for (int l = t; l < 128*NKF; l += 256) sWin[l] = W_in[l];
    for (int l = t; l < DCAT*64; l += 256) sWo1[l] = W_o1[l];
    for (int l = t; l < 64*64;   l += 256) sWo2[l] = W_o2[l];
    sWsem[t] = W_sem[t];
    if (t < NKF) { sbin[t]=b_in[t]; smean[t]=means[t]; sbeta[t]=betas[t]; }
    if (t < 64)  { sbo1[t]=b_o1[t]; sbo2[t]=b_o2[t]; }
    if (t < 4)   sbsem[t]=b_sem[t];
    for (int l = t; l < NN*3; l += 256) sx[l] = x[b*NN*3 + l];
    __syncthreads();

    const int j = t;
    const float dx = sx[j*3+0]-sx[i*3+0];
    const float dy = sx[j*3+1]-sx[i*3+1];
    const float dz = sx[j*3+2]-sx[i*3+2];
    const float ss = dx*dx + dy*dy + dz*dz;
    const float d  = sqrtf(fmaxf(ss, 0.f) + 1e-5f);

    // --- h1 = h_cat @ W_in + b_in ---
    float h1[NKF];
    #pragma unroll
    for (int k = 0; k < NKF; k++) h1[k] = sbin[k];
    const float* hj = sh_h + j*65;
    const float* hi = sh_h + i*65;
    for (int f = 0; f < NF; f++) {
        const float vj = hj[f], vi = hi[f];
        const float2* rj = (const float2*)(sWin + f*NKF);
        const float2* ri = (const float2*)(sWin + (64+f)*NKF);
        #pragma unroll
        for (int k2 = 0; k2 < NKF/2; k2++) {
            float2 wj = rj[k2], wi = ri[k2];
            h1[2*k2]   += vj*wj.x + vi*wi.x;
            h1[2*k2+1] += vj*wj.y + vi*wi.y;
        }
    }

    // --- rbf * h1 ---
    const float em  = __expf(-d);   // ALPHA = 1
    const float cut = (d < 5.f) ? 0.5f*(__cosf(d*0.6283185307179586f)+1.f) : 0.f;
    float rh[NKF];
    #pragma unroll
    for (int k = 0; k < NKF; k++) {
        float dm = em - smean[k];
        rh[k] = cut * __expf(-sbeta[k]*dm*dm) * h1[k];
    }

    // --- t = silu(concat(z) @ W_o1 + b_o1) ---
    float tv[64];
    #pragma unroll
    for (int k = 0; k < 64; k++) tv[k] = sbo1[k];
    auto acc_row = [&](float val, const float* row) {
        const float4* r4 = (const float4*)row;
        #pragma unroll
        for (int q = 0; q < 16; q++) {
            float4 w = r4[q];
            tv[4*q+0] += val*w.x; tv[4*q+1] += val*w.y;
            tv[4*q+2] += val*w.z; tv[4*q+3] += val*w.w;
        }
    };
    for (int f = 0; f < 64; f++) acc_row(hj[f], sWo1 + f*64);
    for (int f = 0; f < 64; f++) acc_row(hi[f], sWo1 + (64+f)*64);
    #pragma unroll
    for (int k = 0; k < NKF; k++) acc_row(rh[k], sWo1 + (128+k)*64);
    acc_row(d, sWo1 + 178*64);
    #pragma unroll
    for (int k = 0; k < 64; k++) tv[k] = siluf(tv[k]);

    // --- h_e = t @ W_o2 + b_o2 ---
    float he[64];
    #pragma unroll
    for (int k = 0; k < 64; k++) he[k] = sbo2[k];
    #pragma unroll
    for (int c = 0; c < 64; c++) {
        const float val = tv[c];
        const float4* r4 = (const float4*)(sWo2 + c*64);
        #pragma unroll
        for (int q = 0; q < 16; q++) {
            float4 w = r4[q];
            he[4*q+0] += val*w.x; he[4*q+1] += val*w.y;
            he[4*q+2] += val*w.z; he[4*q+3] += val*w.w;
        }
    }

    // --- semantic attention logits + celu(alpha=2) + self-mask ---
    float l0=sbsem[0], l1=sbsem[1], l2=sbsem[2], l3=sbsem[3];
    #pragma unroll
    for (int f = 0; f < 64; f++) {
        const float v4 = he[f];
        l0 += v4*sWsem[f*4+0]; l1 += v4*sWsem[f*4+1];
        l2 += v4*sWsem[f*4+2]; l3 += v4*sWsem[f*4+3];
    }
    float lg[4] = {l0, l1, l2, l3};
    #pragma unroll
    for (int hd = 0; hd < 4; hd++) {
        float a = lg[hd];
        a = (a > 0.f) ? a : 2.f*(__expf(0.5f*a) - 1.f);
        if (j == i) a -= 1e5f;
        sLog[hd*NN + j] = a;
    }

    // write h_e (f-major, coalesced)
    #pragma unroll
    for (int f = 0; f < 64; f++) g_he[(bi*NF + f)*NN + j] = he[f];
    __syncthreads();

    // --- softmax over j, one warp per head ---
    const int wp = t >> 5, lane = t & 31;
    if (wp < 4) {
        float m = -1e30f;
        for (int q = 0; q < 8; q++) m = fmaxf(m, sLog[wp*NN + lane + 32*q]);
        #pragma unroll
        for (int o = 16; o; o >>= 1) m = fmaxf(m, __shfl_xor_sync(~0u, m, o));
        float s = 0.f;
        for (int q = 0; q < 8; q++) s += __expf(sLog[wp*NN + lane + 32*q] - m);
        #pragma unroll
        for (int o = 16; o; o >>= 1) s += __shfl_xor_sync(~0u, s, o);
        if (lane == 0) { sRed[wp*2] = m; sRed[wp*2+1] = s; }
    }
    __syncthreads();
    #pragma unroll
    for (int hd = 0; hd < 4; hd++) {
        float a = __expf(sLog[hd*NN + j] - sRed[hd*2]) / sRed[hd*2+1];
        g_att[(bi*NN + j)*4 + hd] = a;
    }
}

// ---------------------------------------------------------------------------
// Kernel B: spatial mixing (U @ W_xmix, tanh, j-reduction) + full node tail.
// One block per (b,i), thread j owns GEMM row j.
// ---------------------------------------------------------------------------
__global__ __launch_bounds__(256, 1) void k_spatial(
    const float* __restrict__ h,    const float* __restrict__ x,
    const float* __restrict__ v,
    const float* __restrict__ W_xmix,
    const float* __restrict__ W_p1, const float* __restrict__ b_p1,
    const float* __restrict__ W_p2, const float* __restrict__ b_p2,
    const float* __restrict__ W_n1, const float* __restrict__ b_n1,
    const float* __restrict__ W_n2, const float* __restrict__ b_n2,
    const float* __restrict__ W_v1, const float* __restrict__ b_v1,
    const float* __restrict__ W_v2, const float* __restrict__ W_vmix,
    float* __restrict__ out)
{
    extern __shared__ float sm[];
    float* sHe   = sm;                 // 64*257 (padded: [f][j])
    float* sAtt  = sHe + 64*257;       // 256*4
    float* sW    = sAtt + 1024;        // 256*64 (W_xmix chunk, later W_p1)
    float* sXh   = sW + 16384;         // 256*4
    float* sComb = sXh + 1024;         // 256*3
    float* sHes  = sComb + 768;        // 256
    float* sPart = sHes + 256;         // 8*192
    float* sHi   = sPart + 1536;       // 64
    float* sT1   = sHi + 64;           // 64
    float* sT2   = sT1 + 64;           // 64
    float* sHn   = sT2 + 64;           // 64
    float* sCn   = sHn + 64;           // 256
    float* sMisc = sCn + 256;          // 16

    const int t  = threadIdx.x;
    const int bi = blockIdx.x;
    const int b  = bi >> 8;
    const int i  = bi & 255;

    for (int l = t; l < 64*NN; l += 256) {
        int f = l >> 8, jj = l & 255;
        sHe[f*257 + jj] = g_he[bi*64*NN + l];
    }
    for (int l = t; l < NN*4; l += 256) sAtt[l] = g_att[bi*NN*4 + l];
    if (t < 64) sHi[t] = h[(b*NN + i)*64 + t];
    {
        const int j = t;
        const float xi0 = x[(b*NN+i)*3+0], xi1 = x[(b*NN+i)*3+1], xi2 = x[(b*NN+i)*3+2];
        const float dx = x[(b*NN+j)*3+0]-xi0;
        const float dy = x[(b*NN+j)*3+1]-xi1;
        const float dz = x[(b*NN+j)*3+2]-xi2;
        const float ssq = dx*dx + dy*dy + dz*dz;
        const float d   = sqrtf(fmaxf(ssq, 0.f) + 1e-5f);
        const float inv = 1.f/(d + 1e-5f);
        sXh[j*4+0] = dx*inv; sXh[j*4+1] = dy*inv; sXh[j*4+2] = dz*inv;
    }
    __syncthreads();

    // h_e_sum[c] = sum_j h_e[j,f]*att[j,hd]
    {
        const int c = t, f = c >> 2, hd = c & 3;
        float s = 0.f;
        for (int jj = 0; jj < NN; jj++) s += sHe[f*257 + jj]*sAtt[jj*4 + hd];
        sHes[c] = s;
    }

    const int j = t;
    const float a0 = sAtt[j*4+0], a1 = sAtt[j*4+1], a2 = sAtt[j*4+2], a3 = sAtt[j*4+3];
    const float xh0 = sXh[j*4+0], xh1 = sXh[j*4+1], xh2 = sXh[j*4+2];
    const int wp = t >> 5, lane = t & 31;

    for (int q = 0; q < 4; q++) {
        __syncthreads();
        // stage W_xmix columns [q*64, q*64+64)
        for (int l = t; l < 4096; l += 256) {
            int c = l >> 4, k4 = l & 15;
            ((float4*)sW)[c*16 + k4] =
                ((const float4*)W_xmix)[(c*256 + q*64)/4 + k4];
        }
        __syncthreads();

        float acc[64];
        #pragma unroll
        for (int k = 0; k < 64; k++) acc[k] = 0.f;
        for (int f = 0; f < 64; f++) {
            const float hv = sHe[f*257 + j];
            const float u0 = hv*a0, u1 = hv*a1, u2 = hv*a2, u3 = hv*a3;
            const float4* r0 = (const float4*)(sW + (f*4+0)*64);
            const float4* r1 = (const float4*)(sW + (f*4+1)*64);
            const float4* r2 = (const float4*)(sW + (f*4+2)*64);
            const float4* r3 = (const float4*)(sW + (f*4+3)*64);
            #pragma unroll
            for (int k4 = 0; k4 < 16; k4++) {
                float4 w0 = r0[k4], w1 = r1[k4], w2 = r2[k4], w3 = r3[k4];
                acc[4*k4+0] += u0*w0.x; acc[4*k4+0] += u1*w1.x; acc[4*k4+0] += u2*w2.x; acc[4*k4+0] += u3*w3.x;
                acc[4*k4+1] += u0*w0.y; acc[4*k4+1] += u1*w1.y; acc[4*k4+1] += u2*w2.y; acc[4*k4+1] += u3*w3.y;
                acc[4*k4+2] += u0*w0.z; acc[4*k4+2] += u1*w1.z; acc[4*k4+2] += u2*w2.z; acc[4*k4+2] += u3*w3.z;
                acc[4*k4+3] += u0*w0.w; acc[4*k4+3] += u1*w1.w; acc[4*k4+3] += u2*w2.w; acc[4*k4+3] += u3*w3.w;
            }
        }

        // tanh + reduce over j (warp shuffles, then 8-partial combine)
        #pragma unroll
        for (int k = 0; k < 64; k++) {
            const float cf = tanhf(acc[k]);
            float p0 = cf*xh0, p1 = cf*xh1, p2 = cf*xh2;
            #pragma unroll
            for (int o = 16; o; o >>= 1) {
                p0 += __shfl_xor_sync(~0u, p0, o);
                p1 += __shfl_xor_sync(~0u, p1, o);
                p2 += __shfl_xor_sync(~0u, p2, o);
            }
            if (lane == 0) {
                sPart[wp*192 + k*3+0] = p0;
                sPart[wp*192 + k*3+1] = p1;
                sPart[wp*192 + k*3+2] = p2;
            }
        }
        __syncthreads();
        if (t < 192) {
            float s = 0.f;
            #pragma unroll
            for (int ww = 0; ww < 8; ww++) s += sPart[ww*192 + t];
            sComb[(q*64 + t/3)*3 + (t%3)] = s*(1.f/NN);
        }
    }
    __syncthreads();

    // ---- node tail ----
    { // comb_norm
        const float c0 = sComb[t*3+0], c1 = sComb[t*3+1], c2 = sComb[t*3+2];
        sCn[t] = c0*c0 + c1*c1 + c2*c2;
    }
    __syncthreads();
    for (int l = t; l < 16384; l += 256) sW[l] = W_p1[l];  // stage W_p1
    __syncthreads();
    if (t < 64) {
        float a = b_p1[t];
        for (int c = 0; c < 256; c++) a += sCn[c]*sW[c*64 + t];
        sT1[t] = siluf(a);
    }
    __syncthreads();
    if (t < 64) {
        float a = b_p2[t];
        for (int c = 0; c < 64; c++) a += sT1[c]*W_p2[c*64 + t];
        sT2[t] = siluf(a);   // h_comb
    }
    __syncthreads();
    if (t < 64) {
        float a = b_n1[t];
        for (int r = 0; r < 64;  r++) a += sHi[r] *W_n1[r*64 + t];
        for (int r = 0; r < 256; r++) a += sHes[r]*W_n1[(64+r)*64 + t];
        for (int r = 0; r < 64;  r++) a += sT2[r] *W_n1[(320+r)*64 + t];
        sT1[t] = siluf(a);
    }
    __syncthreads();
    if (t < 64) {
        float a = b_n2[t];
        for (int c = 0; c < 64; c++) a += sT1[c]*W_n2[c*64 + t];
        const float hn = sHi[t] + siluf(a);
        sHn[t] = hn;
        out[(b*NN + i)*64 + t] = hn;
    }
    __syncthreads();
    if (t < 64) {
        float a = b_v1[t];
        for (int c = 0; c < 64; c++) a += sHn[c]*W_v1[c*64 + t];
        sT1[t] = siluf(a);
    }
    __syncthreads();
    if (wp == 0) {            // v_scale
        float s = sT1[lane]*W_v2[lane] + sT1[lane+32]*W_v2[lane+32];
        #pragma unroll
        for (int o = 16; o; o >>= 1) s += __shfl_xor_sync(~0u, s, o);
        if (lane == 0) sMisc[0] = 2.f/(1.f + __expf(-s));
    }
    if (wp >= 1 && wp <= 3) { // delta_v
        const int dd = wp - 1;
        float s = 0.f;
        for (int q2 = 0; q2 < 8; q2++)
            s += sComb[(lane + 32*q2)*3 + dd]*W_vmix[lane + 32*q2];
        #pragma unroll
        for (int o = 16; o; o >>= 1) s += __shfl_xor_sync(~0u, s, o);
        if (lane == 0) sMisc[1+dd] = s;
    }
    __syncthreads();
    if (t < 3) {
        const float vn = sMisc[1+t] + sMisc[0]*v[(b*NN+i)*3 + t];
        const float xn = x[(b*NN+i)*3 + t] + vn;
        out[NB*NN*64 + (b*NN+i)*3 + t]           = xn;
        out[NB*NN*64 + NB*NN*3 + (b*NN+i)*3 + t] = vn;
    }
}

// ---------------------------------------------------------------------------
extern "C" void kernel_launch(void* const* d_in, const int* in_sizes, int n_in,
                              void* d_out, int out_size)
{
    const float* h      = (const float*)d_in[0];
    const float* x      = (const float*)d_in[1];
    const float* v      = (const float*)d_in[2];
    const float* W_in   = (const float*)d_in[3];
    const float* b_in   = (const float*)d_in[4];
    const float* means  = (const float*)d_in[5];
    const float* betas  = (const float*)d_in[6];
    const float* W_o1   = (const float*)d_in[7];
    const float* b_o1   = (const float*)d_in[8];
    const float* W_o2   = (const float*)d_in[9];
    const float* b_o2   = (const float*)d_in[10];
    const float* W_sem  = (const float*)d_in[11];
    const float* b_sem  = (const float*)d_in[12];
    const float* W_xmix = (const float*)d_in[13];
    const float* W_p1   = (const float*)d_in[14];
    const float* b_p1   = (const float*)d_in[15];
    const float* W_p2   = (const float*)d_in[16];
    const float* b_p2   = (const float*)d_in[17];
    const float* W_n1   = (const float*)d_in[18];
    const float* b_n1   = (const float*)d_in[19];
    const float* W_n2   = (const float*)d_in[20];
    const float* b_n2   = (const float*)d_in[21];
    const float* W_v1   = (const float*)d_in[22];
    const float* b_v1   = (const float*)d_in[23];
    const float* W_v2   = (const float*)d_in[24];
    const float* W_vmix = (const float*)d_in[25];
    float* out = (float*)d_out;

    const size_t smA = (size_t)(NN*65 + 128*NKF + DCAT*64 + 64*64 + 256
                                + 3*NKF + 2*64 + 4 + NN*3 + 4*NN + 16) * sizeof(float);
    const size_t smB = (size_t)(64*257 + 1024 + 16384 + 1024 + 768 + 256
                                + 1536 + 4*64 + 256 + 16) * sizeof(float);

    cudaFuncSetAttribute(k_edge,    cudaFuncAttributeMaxDynamicSharedMemorySize, (int)smA);
    cudaFuncSetAttribute(k_spatial, cudaFuncAttributeMaxDynamicSharedMemorySize, (int)smB);

    k_edge<<<NB*NN, 256, smA>>>(h, x, W_in, b_in, means, betas,
                                W_o1, b_o1, W_o2, b_o2, W_sem, b_sem);
    k_spatial<<<NB*NN, 256, smB>>>(h, x, v, W_xmix, W_p1, b_p1, W_p2, b_p2,
                                   W_n1, b_n1, W_n2, b_n2, W_v1, b_v1,
                                   W_v2, W_vmix, out);
}